// round 4
// baseline (speedup 1.0000x reference)
#include <cuda_runtime.h>

#define Bdim 8
#define Hdim 16
#define Sdim 4096
#define Ddim 64
#define Kdim 256
#define BH (Bdim * Hdim)

// Scratch: projected K (stored transposed [bh][d][k]) and projected V ([bh][k][d]).
// 2 * 128 * 256 * 64 floats = 16 MB total.
__device__ float g_kprojT[(size_t)BH * Kdim * Ddim];
__device__ float g_vproj[(size_t)BH * Kdim * Ddim];

// ---------------------------------------------------------------------------
// Kernel A: per (b,h), C[k,d] = sum_n proj[n,k] * in[bh,n,d] * mask[b,n]
// Block tile: 64 (k) x 64 (d), inner chunk 32 over n. 256 threads, 4x4 regs.
// grid = (4 k-tiles, BH, 2: 0=k-proj, 1=v-proj)
// ---------------------------------------------------------------------------
__global__ __launch_bounds__(256) void kv_proj_kernel(
    const float* __restrict__ kin, const float* __restrict__ vin,
    const float* __restrict__ projk, const float* __restrict__ projv,
    const float* __restrict__ mask)
{
    const int which = blockIdx.z;
    const float* in   = which ? vin   : kin;
    const float* proj = which ? projv : projk;
    float* outp       = which ? g_vproj : g_kprojT;

    const int bh = blockIdx.y;
    const int b  = bh >> 4;           // H = 16
    const int k0 = blockIdx.x * 64;

    __shared__ float As[32][64];      // proj chunk [n][k]
    __shared__ float Bs[32][64];      // input chunk [n][d] * mask

    const int t  = threadIdx.x;
    const int tx = t & 15;            // d sub-tile
    const int ty = t >> 4;            // k sub-tile

    float acc[4][4];
#pragma unroll
    for (int i = 0; i < 4; i++)
#pragma unroll
        for (int j = 0; j < 4; j++) acc[i][j] = 0.0f;

    const float* inb   = in + (size_t)bh * Sdim * Ddim;
    const float* maskb = mask + (size_t)b * Sdim;

    for (int n0 = 0; n0 < Sdim; n0 += 32) {
        // Cooperative load: 32x64 floats each = 512 float4 per array, 2/thread.
#pragma unroll
        for (int l = 0; l < 2; l++) {
            int idx = t + l * 256;
            int row = idx >> 4;
            int c4  = idx & 15;
            float4 a = *(const float4*)&proj[(size_t)(n0 + row) * Kdim + k0 + c4 * 4];
            *(float4*)&As[row][c4 * 4] = a;
            float  m  = maskb[n0 + row];
            float4 bv = *(const float4*)&inb[(size_t)(n0 + row) * Ddim + c4 * 4];
            bv.x *= m; bv.y *= m; bv.z *= m; bv.w *= m;
            *(float4*)&Bs[row][c4 * 4] = bv;
        }
        __syncthreads();

#pragma unroll
        for (int n = 0; n < 32; n++) {
            float4 a  = *(const float4*)&As[n][ty * 4];
            float4 bv = *(const float4*)&Bs[n][tx * 4];
            float av[4] = {a.x, a.y, a.z, a.w};
            float bb[4] = {bv.x, bv.y, bv.z, bv.w};
#pragma unroll
            for (int i = 0; i < 4; i++)
#pragma unroll
                for (int j = 0; j < 4; j++)
                    acc[i][j] += av[i] * bb[j];
        }
        __syncthreads();
    }

    float* ob = outp + (size_t)bh * Kdim * Ddim;
    if (which == 0) {
        // k-proj stored transposed: [d][k]  (so kernel B loads it conflict-free)
#pragma unroll
        for (int i = 0; i < 4; i++)
#pragma unroll
            for (int j = 0; j < 4; j++)
                ob[(size_t)(tx * 4 + j) * Kdim + (k0 + ty * 4 + i)] = acc[i][j];
    } else {
        // v-proj stored natural: [k][d]
#pragma unroll
        for (int i = 0; i < 4; i++)
            *(float4*)&ob[(size_t)(k0 + ty * 4 + i) * Ddim + tx * 4] =
                make_float4(acc[i][0], acc[i][1], acc[i][2], acc[i][3]);
    }
}

// ---------------------------------------------------------------------------
// Kernel B: per (bh, 32-row q tile):
//   scores = q @ k_projT / 8 ; probs = softmax(scores) ; out = probs @ v_proj
// k_proj [d][k] and v_proj [k][d] resident in SMEM (128 KB). scores padded
// to stride 260 to avoid bank conflicts in the softmax pass.
// ---------------------------------------------------------------------------
#define SC_STRIDE 260
#define SMEM_B_BYTES ((32 * 64 + 64 * 256 + 256 * 64 + 32 * SC_STRIDE) * 4)

__global__ __launch_bounds__(256) void attn_kernel(
    const float* __restrict__ q, float* __restrict__ out, float* __restrict__ probs)
{
    extern __shared__ float sm[];
    float* qs = sm;                    // 32 x 64
    float* kp = qs + 32 * 64;          // 64 x 256  ([d][k])
    float* vp = kp + 64 * 256;         // 256 x 64  ([k][d])
    float* sc = vp + 256 * 64;         // 32 x SC_STRIDE

    const int bh = blockIdx.y;
    const int q0 = blockIdx.x * 32;
    const int t  = threadIdx.x;

    // ---- loads ----
    const float* qb = q + ((size_t)bh * Sdim + q0) * Ddim;
#pragma unroll
    for (int l = 0; l < 2; l++) {
        int idx = t + l * 256;
        *(float4*)&qs[idx * 4] = *(const float4*)&qb[(size_t)idx * 4];
    }
    const float* gk = g_kprojT + (size_t)bh * Kdim * Ddim;
    const float* gv = g_vproj  + (size_t)bh * Kdim * Ddim;
#pragma unroll
    for (int l = 0; l < 16; l++) {
        int idx = t + l * 256;
        *(float4*)&kp[idx * 4] = *(const float4*)&gk[(size_t)idx * 4];
        *(float4*)&vp[idx * 4] = *(const float4*)&gv[(size_t)idx * 4];
    }
    __syncthreads();

    // ---- scores: thread = 8 q-rows x 4 k-cols ----
    {
        const int qg = t >> 6;         // 0..3  -> q rows qg*8 .. qg*8+7
        const int kt = t & 63;         // k group (float4)
        float acc[8][4];
#pragma unroll
        for (int r = 0; r < 8; r++)
#pragma unroll
            for (int j = 0; j < 4; j++) acc[r][j] = 0.0f;

        const float* kpp = kp + kt * 4;
        const float* qss = qs + qg * 8 * 64;
        for (int d = 0; d < 64; d++) {
            float4 kv = *(const float4*)&kpp[d * 256];
#pragma unroll
            for (int r = 0; r < 8; r++) {
                float qv = qss[r * 64 + d];
                acc[r][0] += qv * kv.x;
                acc[r][1] += qv * kv.y;
                acc[r][2] += qv * kv.z;
                acc[r][3] += qv * kv.w;
            }
        }
#pragma unroll
        for (int r = 0; r < 8; r++)
            *(float4*)&sc[(qg * 8 + r) * SC_STRIDE + kt * 4] =
                make_float4(acc[r][0] * 0.125f, acc[r][1] * 0.125f,
                            acc[r][2] * 0.125f, acc[r][3] * 0.125f);
    }
    __syncthreads();

    // ---- softmax: 8 lanes per row, 32 values each ----
    {
        const int row = t >> 3;
        const int seg = t & 7;
        float* base = sc + row * SC_STRIDE + seg * 32;
        float v[32];
#pragma unroll
        for (int i = 0; i < 8; i++) {
            float4 f = *(float4*)&base[i * 4];
            v[i * 4] = f.x; v[i * 4 + 1] = f.y; v[i * 4 + 2] = f.z; v[i * 4 + 3] = f.w;
        }
        float mx = -1e30f;
#pragma unroll
        for (int i = 0; i < 32; i++) mx = fmaxf(mx, v[i]);
#pragma unroll
        for (int o = 1; o < 8; o <<= 1)
            mx = fmaxf(mx, __shfl_xor_sync(0xffffffffu, mx, o));
        float sum = 0.0f;
#pragma unroll
        for (int i = 0; i < 32; i++) { v[i] = __expf(v[i] - mx); sum += v[i]; }
#pragma unroll
        for (int o = 1; o < 8; o <<= 1)
            sum += __shfl_xor_sync(0xffffffffu, sum, o);
        float inv = __fdividef(1.0f, sum);
#pragma unroll
        for (int i = 0; i < 8; i++)
            *(float4*)&base[i * 4] =
                make_float4(v[i * 4] * inv, v[i * 4 + 1] * inv,
                            v[i * 4 + 2] * inv, v[i * 4 + 3] * inv);
    }
    __syncthreads();

    // ---- probs write (coalesced from SMEM) ----
    if (probs) {
        float* pb = probs + ((size_t)bh * Sdim + q0) * Kdim;
#pragma unroll
        for (int l = 0; l < 8; l++) {
            int v4 = t + l * 256;
            int qq = v4 >> 6;
            int kc = v4 & 63;
            *(float4*)&pb[(size_t)qq * Kdim + kc * 4] =
                *(const float4*)&sc[qq * SC_STRIDE + kc * 4];
        }
    }

    // ---- out = probs @ v_proj : thread = 2 q-rows x 4 d-cols ----
    {
        const int qg2 = t >> 4;        // 0..15 -> q rows 2*qg2, 2*qg2+1
        const int dg  = t & 15;        // d group (float4)
        float a0[4] = {0, 0, 0, 0}, a1[4] = {0, 0, 0, 0};
        const float* vpp = vp + dg * 4;
        const float* s0  = sc + (qg2 * 2) * SC_STRIDE;
        const float* s1  = s0 + SC_STRIDE;
        for (int k = 0; k < 256; k++) {
            float4 v4 = *(const float4*)&vpp[k * 64];
            float p0 = s0[k], p1 = s1[k];
            a0[0] += p0 * v4.x; a0[1] += p0 * v4.y; a0[2] += p0 * v4.z; a0[3] += p0 * v4.w;
            a1[0] += p1 * v4.x; a1[1] += p1 * v4.y; a1[2] += p1 * v4.z; a1[3] += p1 * v4.w;
        }
        float* ob = out + ((size_t)bh * Sdim + q0) * Ddim;
        *(float4*)&ob[(size_t)(qg2 * 2) * Ddim + dg * 4] =
            make_float4(a0[0], a0[1], a0[2], a0[3]);
        *(float4*)&ob[(size_t)(qg2 * 2 + 1) * Ddim + dg * 4] =
            make_float4(a1[0], a1[1], a1[2], a1[3]);
    }
}

// ---------------------------------------------------------------------------
extern "C" void kernel_launch(void* const* d_in, const int* in_sizes, int n_in,
                              void* d_out, int out_size)
{
    const float* q    = (const float*)d_in[0];
    const float* k    = (const float*)d_in[1];
    const float* v    = (const float*)d_in[2];
    const float* mask = (const float*)d_in[3];
    const float* pk   = (const float*)d_in[4];
    const float* pv   = (const float*)d_in[5];

    float* out = (float*)d_out;
    const long OUT_ELEMS = (long)BH * Sdim * Ddim;   // 33,554,432
    float* probs = ((long)out_size > OUT_ELEMS) ? (out + OUT_ELEMS) : nullptr;

    cudaFuncSetAttribute(attn_kernel, cudaFuncAttributeMaxDynamicSharedMemorySize,
                         SMEM_B_BYTES);

    dim3 gA(Kdim / 64, BH, 2);
    kv_proj_kernel<<<gA, 256>>>(k, v, pk, pv, mask);

    dim3 gB(Sdim / 32, BH);
    attn_kernel<<<gB, 256, SMEM_B_BYTES>>>(q, out, probs);
}